// round 15
// baseline (speedup 1.0000x reference)
#include <cuda_runtime.h>
#include <cstdint>

// (B, D, H, W) = (2, 192, 192, 192) fp32
#define DD 192
#define HH 192
#define WW 192
#define PLANE 36864
#define VOL   7077888

#define NT 256
// raw stage: [2 sets][3 sl][2 fld][24 rows][44]
#define ST_ROW 44
#define ST_FIELD 1056
#define ST_SLICE 2112
#define ST_SET   6336
// W-sums: [2 par][3 sl][3 fld][24 rows][33]
#define WS_STR 33
#define WS_FLD 792
#define WS_SL  2376
#define WS_PAR 7128

#define INV_VOL (1.0f/729.0f)
#define EPS 1e-5f

#define SMEM_FLOATS (2*ST_SET + 2*WS_PAR)   // 26928
#define SMEM_BYTES  (SMEM_FLOATS*4)         // 107712 -> 2 CTAs/SM (215.4KB)

// R15: R12's balanced stages, tri-batched (1 barrier / 3 slices, 36 regions).
//   region i: fill(trio i+1) | HD(trio i-1) all threads | W(trio i) all threads
__global__ void __launch_bounds__(NT, 2)
lncc_fusedA(const float* __restrict__ gt, const float* __restrict__ gp,
            float* __restrict__ out)
{
    extern __shared__ float sm[];
    float* stg  = sm;                     // raw slices
    float* wsum = sm + 2*ST_SET;          // W-sums

    const int tid = threadIdx.x;
    const int bx = blockIdx.x;
    const int wt = bx % 6;
    const int ht = (bx/6) % 12;
    const int dc = (bx/72) % 2;
    const int bb = bx/144;
    const int w0 = wt*32, h0 = ht*16, d0 = dc*96;
    const int gvol = bb*VOL;

    // zero raw stages once: OOB halo lanes never overwritten -> SAME padding
    for (int i = tid; i < 2*ST_SET; i += NT) stg[i] = 0.f;

    const uint32_t stg_base = (uint32_t)__cvta_generic_to_shared(stg);

    // ---- fill geometry: per slice 480 tasks = 48 rowf x 10 float4 ----
    const float* fsrc[2]; uint32_t fdst[2]; bool fok[2];
#pragma unroll
    for (int k2 = 0; k2 < 2; ++k2) {
        const int task = tid + k2*NT;
        bool ok = task < 480;
        const int chunk = task % 10;
        const int rowf  = task / 10;
        const int fld   = rowf >= 24 ? 1 : 0;
        const int row   = rowf - fld*24;
        const int gh = h0 - 4 + row;
        const int gw = w0 - 4 + chunk*4;
        ok = ok && (unsigned)gh < HH && (unsigned)gw < WW;
        fok[k2]  = ok;
        fsrc[k2] = (fld ? gp : gt) + (gvol + gh*WW + gw);
        fdst[k2] = stg_base + (uint32_t)(fld*ST_FIELD + row*ST_ROW + chunk*4)*4u;
    }

    auto fill_trio = [&](int p) {          // slices j = 3p..3p+2, set p&1
        const uint32_t setoff = (uint32_t)((p&1)*ST_SET)*4u;
#pragma unroll
        for (int sl = 0; sl < 3; ++sl) {
            const int dz = d0 - 4 + 3*p + sl;
            if ((unsigned)dz < DD) {
                const int off = dz*PLANE;
                const uint32_t dsb = setoff + (uint32_t)(sl*ST_SLICE)*4u;
#pragma unroll
                for (int k2 = 0; k2 < 2; ++k2)
                    if (fok[k2])
                        asm volatile("cp.async.cg.shared.global [%0], [%1], 16;"
                                     :: "r"(fdst[k2]+dsb), "l"(fsrc[k2]+off));
            }
        }
        asm volatile("cp.async.commit_group;");
    };

    // ---- W geometry: 288 tasks/trio = 3 sl x 24 rows x 4 segs of 8 ----
    // task IDs: tid (all) and 256+tid (tid<32)
    int  w_sl[2], w_ro[2], w_wo[2];
#pragma unroll
    for (int k2 = 0; k2 < 2; ++k2) {
        const int task = tid + k2*256;
        const int sl   = task / 96;
        const int rest = task - sl*96;
        const int wr   = rest >> 2, ws8 = (rest & 3) << 3;
        w_sl[k2] = sl;
        w_ro[k2] = sl*ST_SLICE + wr*ST_ROW + ws8;
        w_wo[k2] = sl*WS_SL + wr*WS_STR + ws8;
    }

    auto wtask = [&](int k2, int set, int par, int j0) {
        const int dz = d0 - 4 + j0 + w_sl[k2];
        float* o = wsum + par*WS_PAR + w_wo[k2];
        if ((unsigned)dz < DD) {
            const float* pt = stg + set*ST_SET + w_ro[k2];
            const float4 T0 = ((const float4*)pt)[0];
            const float4 T1 = ((const float4*)pt)[1];
            const float4 T2 = ((const float4*)pt)[2];
            const float4 T3 = ((const float4*)pt)[3];
            const float* pq = pt + ST_FIELD;
            const float4 P0 = ((const float4*)pq)[0];
            const float4 P1 = ((const float4*)pq)[1];
            const float4 P2 = ((const float4*)pq)[2];
            const float4 P3 = ((const float4*)pq)[3];
            const float t[16] = {T0.x,T0.y,T0.z,T0.w, T1.x,T1.y,T1.z,T1.w,
                                 T2.x,T2.y,T2.z,T2.w, T3.x,T3.y,T3.z,T3.w};
            const float p2[16] = {P0.x,P0.y,P0.z,P0.w, P1.x,P1.y,P1.z,P1.w,
                                  P2.x,P2.y,P2.z,P2.w, P3.x,P3.y,P3.z,P3.w};
            float s0 = 0.f, s1 = 0.f, s2 = 0.f;
#pragma unroll
            for (int k = 0; k < 9; ++k) {
                s0 += t[k]; s1 += p2[k]; s2 = fmaf(t[k], p2[k], s2);
            }
            o[0] = s0; o[WS_FLD] = s1; o[2*WS_FLD] = s2;
#pragma unroll
            for (int q = 1; q < 8; ++q) {
                s0 += t[8+q] - t[q-1];
                s1 += p2[8+q] - p2[q-1];
                s2 = fmaf(t[8+q], p2[8+q], s2);
                s2 = fmaf(-t[q-1], p2[q-1], s2);
                o[q] = s0; o[WS_FLD+q] = s1; o[2*WS_FLD+q] = s2;
            }
        } else {
#pragma unroll
            for (int q = 0; q < 8; ++q) {
                o[q] = 0.f; o[WS_FLD+q] = 0.f; o[2*WS_FLD+q] = 0.f;
            }
        }
    };

    // ---- HD geometry: all threads, 2 h-rows each ----
    const int tx = tid & 31, ty = tid >> 5;
    const int rb = ty << 1;
    const int rbtx = rb*WS_STR + tx;
    const int obase = gvol + (h0 + rb)*WW + w0 + tx;

    float ring[48], S[6];
#pragma unroll
    for (int q = 0; q < 48; ++q) ring[q] = 0.f;
#pragma unroll
    for (int q = 0; q < 6; ++q) S[q] = 0.f;

// ingest slice j_ = j0h + C from parity PAR into ring slot PH (+ epilogue)
#define HD_SLICE(PAR, C, PH) do {                                            \
    const int j_ = j0h + (C);                                                \
    if (j_ <= 103) {                                                         \
        const float* hb = wsum + (PAR)*WS_PAR + (C)*WS_SL + rbtx;            \
        float u[10];                                                         \
        float a0,a1,a2,b0,b1,b2;                                             \
        _Pragma("unroll") for (int k=0;k<10;++k) u[k]=hb[k*WS_STR];          \
        a0=((u[0]+u[1])+(u[2]+u[3]))+((u[4]+u[5])+(u[6]+u[7]))+u[8];         \
        b0=a0-u[0]+u[9];                                                     \
        _Pragma("unroll") for (int k=0;k<10;++k) u[k]=hb[WS_FLD+k*WS_STR];   \
        a1=((u[0]+u[1])+(u[2]+u[3]))+((u[4]+u[5])+(u[6]+u[7]))+u[8];         \
        b1=a1-u[0]+u[9];                                                     \
        _Pragma("unroll") for (int k=0;k<10;++k) u[k]=hb[2*WS_FLD+k*WS_STR]; \
        a2=((u[0]+u[1])+(u[2]+u[3]))+((u[4]+u[5])+(u[6]+u[7]))+u[8];         \
        b2=a2-u[0]+u[9];                                                     \
        S[0]+=a0; S[1]+=a1; S[2]+=a2; S[3]+=b0; S[4]+=b1; S[5]+=b2;          \
        if (j_ >= 8) {                                                       \
            const float ca = S[2]-S[1]*S[0]*INV_VOL;                         \
            const float cb = S[5]-S[4]*S[3]*INV_VOL;                         \
            const int oo = obase + (d0 + j_ - 8)*PLANE;                      \
            out[oo]    = fmaf(ca,ca,EPS);                                    \
            out[oo+WW] = fmaf(cb,cb,EPS);                                    \
        }                                                                    \
        S[0]-=ring[(PH)*6+0]; S[1]-=ring[(PH)*6+1]; S[2]-=ring[(PH)*6+2];    \
        S[3]-=ring[(PH)*6+3]; S[4]-=ring[(PH)*6+4]; S[5]-=ring[(PH)*6+5];    \
        ring[(PH)*6+0]=a0; ring[(PH)*6+1]=a1; ring[(PH)*6+2]=a2;             \
        ring[(PH)*6+3]=b0; ring[(PH)*6+4]=b1; ring[(PH)*6+5]=b2;             \
    }                                                                        \
} while(0)

// one region: compile-time R (= i mod 8), runtime i
#define REGION(R, I) do {                                                    \
    asm volatile("cp.async.wait_group 0;");                                  \
    __syncthreads();                                                         \
    if ((I) <= 33) fill_trio((I)+1);                                         \
    if ((I) >= 1) {                                                          \
        const int j0h = 3*((I)-1);                                           \
        HD_SLICE(((R)+1)&1, 0, (3*(R)+5)&7);                                 \
        HD_SLICE(((R)+1)&1, 1, (3*(R)+6)&7);                                 \
        HD_SLICE(((R)+1)&1, 2, (3*(R)+7)&7);                                 \
    }                                                                        \
    if ((I) <= 34) {                                                         \
        wtask(0, (R)&1, (R)&1, 3*(I));                                       \
        if (tid < 32) wtask(1, (R)&1, (R)&1, 3*(I));                         \
    }                                                                        \
} while(0)

    __syncthreads();                 // raw zeros visible
    fill_trio(0);

    // regions 0..31 (4 x unrolled 8), then tail regions 32..35
    for (int a = 0; a < 4; ++a) {
#pragma unroll
        for (int r = 0; r < 8; ++r) {
            const int i = a*8 + r;
            REGION(r, i);
        }
    }
#pragma unroll
    for (int r = 0; r < 4; ++r) {
        const int i = 32 + r;
        REGION(r, i);
    }
#undef REGION
#undef HD_SLICE
}

extern "C" void kernel_launch(void* const* d_in, const int* in_sizes, int n_in,
                              void* d_out, int out_size) {
    const float* y_true = (const float*)d_in[0];
    const float* y_pred = (const float*)d_in[1];
    float* out = (float*)d_out;

    cudaFuncSetAttribute(lncc_fusedA,
                         cudaFuncAttributeMaxDynamicSharedMemorySize, SMEM_BYTES);

    // 6 w-tiles x 12 h-tiles x 2 d-chunks x 2 batches = 288 blocks (2 CTAs/SM)
    lncc_fusedA<<<288, NT, SMEM_BYTES>>>(y_true, y_pred, out);
}

// round 16
// speedup vs baseline: 1.1414x; 1.1414x over previous
#include <cuda_runtime.h>
#include <cstdint>

// (B, D, H, W) = (2, 192, 192, 192) fp32
#define DD 192
#define HH 192
#define WW 192
#define PLANE 36864
#define VOL   7077888

#define NT 256
#define INR 24                     // staged rows = 16 + 8 halo
#define ST_ROW 44                  // stage row stride (floats)
#define ST_FIELD 1056              // 24*44
#define ST_SLICE 2112              // t + p
#define WSTR 36                    // W-sum row stride (16B aligned)
#define WFLD 864                   // 24*36 per field
#define WSL  2592                  // 3 fields per slice
#define WPAR 5184                  // 2 slices per parity set

#define INV_VOL (1.0f/729.0f)
#define EPS 1e-5f

// smem: 6 slice stage bufs (3 sets x 2) + 2 W-sum parity sets (2 slices each)
#define SMEM_FLOATS (6*ST_SLICE + 2*WPAR)   // 23040
#define SMEM_BYTES  (SMEM_FLOATS*4)          // 92160 -> 2 CTAs/SM

// R16: exact R12 pipeline (pair-batched, lookahead-2, all warps per stage)
// with 16B-aligned W-sum layout and vectorized STS.128 w-stage stores.
__global__ void __launch_bounds__(NT, 2)
lncc_fusedB(const float* __restrict__ gt, const float* __restrict__ gp,
            float* __restrict__ out)
{
    extern __shared__ float sm[];
    float* stg = sm;                 // [3 sets][2 sl][2 fld][24][44]
    float* ws  = sm + 6*ST_SLICE;    // [2 par][2 sl][3 fld][24][36]

    const int tid = threadIdx.x;
    const int bx = blockIdx.x;
    const int wt = bx % 6;
    const int ht = (bx/6) % 12;
    const int dc = (bx/72) % 2;
    const int bb = bx/144;
    const int w0 = wt*32, h0 = ht*16, d0 = dc*96;
    const int gvol = bb*VOL;

    // zero stage once: OOB (h/w halo) lanes are never overwritten
    for (int i = tid; i < 6*ST_SLICE; i += NT) stg[i] = 0.f;

    const uint32_t stg_base = (uint32_t)__cvta_generic_to_shared(stg);

    // ---- hoisted fill geometry: 480 tasks = 48 rowf x 10 float4 chunks ----
    const float* fsrc[2]; uint32_t fdst[2]; bool fok[2];
#pragma unroll
    for (int k = 0; k < 2; ++k) {
        const int task = tid + k*NT;
        bool ok = task < 480;
        const int chunk = task % 10;
        const int rowf  = task / 10;
        const int fld   = rowf >= INR ? 1 : 0;
        const int row   = rowf - fld*INR;
        const int gh = h0 - 4 + row;
        const int gw = w0 - 4 + chunk*4;
        ok = ok && (unsigned)gh < HH && (unsigned)gw < WW;
        fok[k]  = ok;
        fsrc[k] = (fld ? gp : gt) + (gvol + gh*WW + gw);
        fdst[k] = stg_base + (uint32_t)(fld*ST_FIELD + row*ST_ROW + chunk*4)*4u;
    }

    auto fill_pair = [&](int pair, int rset) {
#pragma unroll
        for (int sl = 0; sl < 2; ++sl) {
            const int dz = d0 - 4 + 2*pair + sl;
            if ((unsigned)dz < DD) {
                const int off = dz*PLANE;
                const uint32_t dsb = (uint32_t)((rset*2+sl)*ST_SLICE)*4u;
#pragma unroll
                for (int k = 0; k < 2; ++k)
                    if (fok[k])
                        asm volatile("cp.async.cg.shared.global [%0], [%1], 16;"
                                     :: "r"(fdst[k]+dsb), "l"(fsrc[k]+off));
            }
        }
        asm volatile("cp.async.commit_group;");
    };

    // ---- w geometry: per pair 192 tasks = 2 sl x 24 rows x 4 segs8 ----
    const bool wact = tid < 192;
    const int wsl  = tid >= 96 ? 1 : 0;
    const int wsub = tid - wsl*96;
    const int wr   = wsub >> 2, ws4 = wsub & 3;
    const int wroff = wsl*ST_SLICE + wr*ST_ROW + ws4*8;   // + rset*2*ST_SLICE
    const int wcout = wsl*WSL + wr*WSTR + ws4*8;          // + par*WPAR

    auto wstage_pair = [&](int pair, int rset, int par) {
        if (!wact) return;
        const int dz = d0 - 4 + 2*pair + wsl;
        float* o = ws + par*WPAR + wcout;
        if ((unsigned)dz < DD) {
            const float* pt = stg + rset*2*ST_SLICE + wroff;
            const float4 T0 = ((const float4*)pt)[0];
            const float4 T1 = ((const float4*)pt)[1];
            const float4 T2 = ((const float4*)pt)[2];
            const float4 T3 = ((const float4*)pt)[3];
            const float* pq = pt + ST_FIELD;
            const float4 P0 = ((const float4*)pq)[0];
            const float4 P1 = ((const float4*)pq)[1];
            const float4 P2 = ((const float4*)pq)[2];
            const float4 P3 = ((const float4*)pq)[3];
            const float t[16] = {T0.x,T0.y,T0.z,T0.w, T1.x,T1.y,T1.z,T1.w,
                                 T2.x,T2.y,T2.z,T2.w, T3.x,T3.y,T3.z,T3.w};
            const float p[16] = {P0.x,P0.y,P0.z,P0.w, P1.x,P1.y,P1.z,P1.w,
                                 P2.x,P2.y,P2.z,P2.w, P3.x,P3.y,P3.z,P3.w};
            float r[8];
            // field 0: sum_t
            {
                float s = 0.f;
#pragma unroll
                for (int k = 0; k < 9; ++k) s += t[k];
                r[0] = s;
#pragma unroll
                for (int q = 1; q < 8; ++q) { s += t[8+q] - t[q-1]; r[q] = s; }
                *(float4*)(o)     = make_float4(r[0],r[1],r[2],r[3]);
                *(float4*)(o + 4) = make_float4(r[4],r[5],r[6],r[7]);
            }
            // field 1: sum_p
            {
                float s = 0.f;
#pragma unroll
                for (int k = 0; k < 9; ++k) s += p[k];
                r[0] = s;
#pragma unroll
                for (int q = 1; q < 8; ++q) { s += p[8+q] - p[q-1]; r[q] = s; }
                *(float4*)(o + WFLD)     = make_float4(r[0],r[1],r[2],r[3]);
                *(float4*)(o + WFLD + 4) = make_float4(r[4],r[5],r[6],r[7]);
            }
            // field 2: sum_tp (products, fmaf slide)
            {
                float s = 0.f;
#pragma unroll
                for (int k = 0; k < 9; ++k) s = fmaf(t[k], p[k], s);
                r[0] = s;
#pragma unroll
                for (int q = 1; q < 8; ++q) {
                    s = fmaf(t[8+q], p[8+q], s);
                    s = fmaf(-t[q-1], p[q-1], s);
                    r[q] = s;
                }
                *(float4*)(o + 2*WFLD)     = make_float4(r[0],r[1],r[2],r[3]);
                *(float4*)(o + 2*WFLD + 4) = make_float4(r[4],r[5],r[6],r[7]);
            }
        } else {
            const float4 z = make_float4(0.f,0.f,0.f,0.f);
            *(float4*)(o)              = z;
            *(float4*)(o + 4)          = z;
            *(float4*)(o + WFLD)       = z;
            *(float4*)(o + WFLD + 4)   = z;
            *(float4*)(o + 2*WFLD)     = z;
            *(float4*)(o + 2*WFLD + 4) = z;
        }
    };

    // ---- h geometry: 2 consecutive h-outputs per thread ----
    const int ty = tid >> 5, tx = tid & 31;
    const int rb = ty << 1;
    const int rbtx = rb*WSTR + tx;
    const int obase = gvol + (h0+rb)*WW + w0 + tx;

    float ring[48], S[6];
#pragma unroll
    for (int q = 0; q < 48; ++q) ring[q] = 0.f;
#pragma unroll
    for (int q = 0; q < 6; ++q) S[q] = 0.f;

// ingest one slice's HW-sums into ring + fused epilogue; PH compile-time
#define H_SLICE(PAR, SL, PH, DOOUT, DOFS) do {                               \
    const float* hb = ws + (PAR)*WPAR + (SL)*WSL + rbtx;                     \
    float u[10];                                                             \
    float a0,a1,a2,b0,b1,b2;                                                 \
    _Pragma("unroll") for (int k=0;k<10;++k) u[k]=hb[k*WSTR];                \
    a0=((u[0]+u[1])+(u[2]+u[3]))+((u[4]+u[5])+(u[6]+u[7]))+u[8];             \
    b0=a0-u[0]+u[9];                                                         \
    _Pragma("unroll") for (int k=0;k<10;++k) u[k]=hb[WFLD+k*WSTR];           \
    a1=((u[0]+u[1])+(u[2]+u[3]))+((u[4]+u[5])+(u[6]+u[7]))+u[8];             \
    b1=a1-u[0]+u[9];                                                         \
    _Pragma("unroll") for (int k=0;k<10;++k) u[k]=hb[2*WFLD+k*WSTR];         \
    a2=((u[0]+u[1])+(u[2]+u[3]))+((u[4]+u[5])+(u[6]+u[7]))+u[8];             \
    b2=a2-u[0]+u[9];                                                         \
    S[0]+=a0; S[1]+=a1; S[2]+=a2; S[3]+=b0; S[4]+=b1; S[5]+=b2;              \
    if (DOOUT) {                                                             \
        const float ca = S[2]-S[1]*S[0]*INV_VOL;                             \
        const float cb = S[5]-S[4]*S[3]*INV_VOL;                             \
        const int oo = obase + (DOFS)*PLANE;                                 \
        out[oo]      = fmaf(ca,ca,EPS);                                      \
        out[oo + WW] = fmaf(cb,cb,EPS);                                      \
    }                                                                        \
    S[0]-=ring[(PH)*6+0]; S[1]-=ring[(PH)*6+1]; S[2]-=ring[(PH)*6+2];        \
    S[3]-=ring[(PH)*6+3]; S[4]-=ring[(PH)*6+4]; S[5]-=ring[(PH)*6+5];        \
    ring[(PH)*6+0]=a0; ring[(PH)*6+1]=a1; ring[(PH)*6+2]=a2;                 \
    ring[(PH)*6+3]=b0; ring[(PH)*6+4]=b1; ring[(PH)*6+5]=b2;                 \
} while(0)

    __syncthreads();                 // stage zeros visible
    fill_pair(0, 0);
    fill_pair(1, 1);

    // 52 pairs (104 slices: dz = d0-4 .. d0+99)
    for (int bq = 0; bq < 13; ++bq) {
#pragma unroll
        for (int ii = 0; ii < 4; ++ii) {
            const int i = bq*4 + ii;          // pair index 0..51
            asm volatile("cp.async.wait_group 1;");
            __syncthreads();
            if (i > 0) {
                const bool dout = (i >= 5);
                // h-slices t0=2i-2, t1=2i-1 from parity (i-1)&1 = (ii+1)&1
                H_SLICE((ii+1)&1, 0, (2*ii+6)&7, dout, d0+2*i-10);
                H_SLICE((ii+1)&1, 1, (2*ii+7)&7, dout, d0+2*i-9);
            }
            wstage_pair(i, i%3, ii&1);
            if (i <= 49) fill_pair(i+2, (i+2)%3);
            else         asm volatile("cp.async.commit_group;");
        }
    }
    // final pair (t=102,103 -> outputs d0+94, d0+95)
    __syncthreads();
    H_SLICE(1, 0, 6, true, d0+94);
    H_SLICE(1, 1, 7, true, d0+95);
#undef H_SLICE
}

extern "C" void kernel_launch(void* const* d_in, const int* in_sizes, int n_in,
                              void* d_out, int out_size) {
    const float* y_true = (const float*)d_in[0];
    const float* y_pred = (const float*)d_in[1];
    float* out = (float*)d_out;

    cudaFuncSetAttribute(lncc_fusedB,
                         cudaFuncAttributeMaxDynamicSharedMemorySize, SMEM_BYTES);

    // 6 w-tiles x 12 h-tiles x 2 d-chunks x 2 batches = 288 blocks (2 CTAs/SM)
    lncc_fusedB<<<288, NT, SMEM_BYTES>>>(y_true, y_pred, out);
}